// round 7
// baseline (speedup 1.0000x reference)
#include <cuda_runtime.h>
#include <math.h>

// output_spikes (B=16, T=2000, N=512) float32, target_cv (512) float32.
#define NNEUR 512
#define NG    128                  // neuron groups of 4 (float4)
#define LTOT  32000                // B*T
#define NBLK  444                  // 3 blocks/SM, single wave (148*3)
#define SUBS  (NBLK * 4)           // 1776 sub-chunks (4 row-slices per block)
#define RB    (LTOT / SUBS)        // 18
#define RREM  (LTOT % SUBS)        // 32 (sub-chunks 0..31 get 19 rows)
#define RED_THREADS 512            // pow2 >= NBLK for the pass-2 tree
#define BIGF  1.0e6f               // sentinel for first-spike min trick

// Per-(neuron, block) partial: {k, first_spike_l, last_spike_l, bits(sum_d2)}
__device__ int4  g_partial[NNEUR * NBLK];
__device__ float g_accum;
__device__ int   g_cnt;

// Ordered combine of two ADJACENT segments (a before b). Identity: k == 0.
__device__ __forceinline__ int4 comb(int4 a, int4 b) {
    if (b.x == 0) return a;
    if (a.x == 0) return b;
    float d = (float)(b.y - a.z);                       // cross-segment ISI
    float s = __int_as_float(a.w) + __int_as_float(b.w) + d * d;
    return make_int4(a.x + b.x, a.y, b.z, __float_as_int(s));
}

// Gap-counter update. v in {0,1}. g = gap since last spike (or since rel=0).
// Recorded gap at a spike includes the bogus first-gap (= t_first), corrected
// at flush. relmB = rel - BIGF, rel 1-based local row.
#define PE(v, j, relmB)                                      \
    do {                                                     \
        float d_ = gp[j] + 1.0f;                             \
        float m_ = (v) * d_;                                 \
        s[j]  = fmaf(m_, d_, s[j]);                          \
        gp[j] = d_ - m_;                                     \
        kf[j] += (v);                                        \
        tf[j] = fminf(tf[j], fmaf((v), (relmB), BIGF));      \
    } while (0)

#define P4(vec, relmB)               \
    do {                             \
        PE((vec).x, 0, (relmB));     \
        PE((vec).y, 1, (relmB));     \
        PE((vec).z, 2, (relmB));     \
        PE((vec).w, 3, (relmB));     \
    } while (0)

#define PROW(vec, rr)  P4((vec), (float)((rr) + 1) - BIGF)

__global__ __launch_bounds__(512, 3) void cv_pass1(const float* __restrict__ x) {
    const int tid   = threadIdx.x;
    const int slice = tid >> 7;          // 0..3 : row-slice within block
    const int g     = tid & (NG - 1);    // 0..127: neuron group (4 neurons)
    const int sc    = blockIdx.x * 4 + slice;      // global sub-chunk
    if (blockIdx.x == 0 && tid == 0) { g_accum = 0.0f; g_cnt = 0; }

    const int start = sc * RB + min(sc, RREM);
    const int rows  = RB + (sc < RREM ? 1 : 0);    // 18 or 19

    float kf[4] = {0.f, 0.f, 0.f, 0.f};
    float gp[4] = {0.f, 0.f, 0.f, 0.f};            // gap counter
    float tf[4] = {BIGF, BIGF, BIGF, BIGF};        // running first (1-based local)
    float s[4]  = {0.f, 0.f, 0.f, 0.f};            // sum d^2 incl. bogus first term

    const float4* p = (const float4*)x + (size_t)start * NG + g;
    int r = 0;
    for (; r + 4 <= rows; r += 4) {
        // 4 independent LDG.128, branchless body -> ptxas front-batches them
        float4 v0 = p[0 * NG];
        float4 v1 = p[1 * NG];
        float4 v2 = p[2 * NG];
        float4 v3 = p[3 * NG];
        p += 4 * NG;
        PROW(v0, r + 0); PROW(v1, r + 1); PROW(v2, r + 2); PROW(v3, r + 3);
    }
    for (; r < rows; ++r) {
        float4 v = p[0];
        p += NG;
        PROW(v, r);
    }

    // Flush: t_last = rows - g_end (1-based local); subtract bogus first gap^2.
    __shared__ int4 sp[4][NNEUR];
#pragma unroll
    for (int j = 0; j < 4; ++j) {
        int kk = (int)kf[j];
        int4 part;
        if (kk > 0) {
            int   tfirst = (int)tf[j];
            int   tlast  = rows - (int)gp[j];
            float sc_    = s[j] - tf[j] * tf[j];
            part = make_int4(kk, start + tfirst - 1, start + tlast - 1,
                             __float_as_int(sc_));
        } else {
            part = make_int4(0, 0, 0, 0);
        }
        sp[slice][g * 4 + j] = part;
    }
    __syncthreads();

    if (slice == 0) {
#pragma unroll
        for (int j = 0; j < 4; ++j) {
            const int n = g * 4 + j;
            int4 a = sp[0][n];
            a = comb(a, sp[1][n]);
            a = comb(a, sp[2][n]);
            a = comb(a, sp[3][n]);
            g_partial[(size_t)n * NBLK + blockIdx.x] = a;
        }
    }
}

// One block per neuron: adjacent-pair tree over the 444 block partials.
__global__ __launch_bounds__(RED_THREADS) void cv_pass2(const float* __restrict__ target) {
    const int n   = blockIdx.x;
    const int tid = threadIdx.x;

    __shared__ int4 sm[RED_THREADS];

    int4 part = make_int4(0, 0, 0, 0);
    if (tid < NBLK)
        part = g_partial[(size_t)n * NBLK + tid];   // coalesced along chunk axis
    sm[tid] = part;
    __syncthreads();

    for (int lvl = RED_THREADS; lvl > 1; lvl >>= 1) {
        const int half = lvl >> 1;
        int4 res;
        if (tid < half)
            res = comb(sm[2 * tid], sm[2 * tid + 1]);   // adjacent -> contiguous
        __syncthreads();
        if (tid < half)
            sm[tid] = res;
        __syncthreads();
    }

    if (tid == 0) {
        int4 tot = sm[0];
        int kk = tot.x;
        if (kk >= 3) {
            float cnt   = (float)(kk - 1);            // number of ISIs
            float sum_d = (float)(tot.z - tot.y);     // telescoping sum of ISIs
            float mean  = sum_d / cnt;
            if (mean > 0.0f) {
                // sum((d-mean)^2) = sum_d2 - 2*mean*sum_d + cnt*mean^2
                float var = (__int_as_float(tot.w) - 2.0f * mean * sum_d + cnt * mean * mean)
                            / fmaxf(cnt - 1.0f, 1.0f);   // unbiased (correction=1)
                float stdv = (var > 0.0f) ? sqrtf(var) : 0.0f;
                float cv   = stdv / fmaxf(mean, 1e-12f);
                float diff = cv - target[n];
                atomicAdd(&g_accum, diff * diff);
                atomicAdd(&g_cnt, 1);
            }
        }
    }
}

__global__ void cv_pass3(float* __restrict__ out) {
    out[0] = g_accum / fmaxf((float)g_cnt, 1.0f);
}

extern "C" void kernel_launch(void* const* d_in, const int* in_sizes, int n_in,
                              void* d_out, int out_size) {
    const float* spikes = (const float*)d_in[0];   // (16, 2000, 512) float32
    const float* target = (const float*)d_in[1];   // (512,) float32
    float* out = (float*)d_out;                    // scalar float32

    cv_pass1<<<NBLK, 512>>>(spikes);
    cv_pass2<<<NNEUR, RED_THREADS>>>(target);
    cv_pass3<<<1, 1>>>(out);
}

// round 9
// speedup vs baseline: 1.0364x; 1.0364x over previous
#include <cuda_runtime.h>
#include <math.h>

// output_spikes (B=16, T=2000, N=512) float32, target_cv (512) float32.
#define NNEUR 512
#define NG    128                  // neuron groups of 4 (float4)
#define LTOT  32000                // B*T
#define NBLK  296                  // 2 blocks/SM, single wave
#define SUBS  (NBLK * 4)           // 1184 sub-chunks (4 row-slices per block)
#define RB    (LTOT / SUBS)        // 27
#define RREM  (LTOT % SUBS)        // 32 (sub-chunks 0..31 get 28 rows)
#define RED_THREADS 512            // pow2 >= NBLK for the pass-2 tree

typedef unsigned long long u64;

// packed {1.0f,1.0f} and {-1.0f,-1.0f}
#define ONE2_C   0x3F8000003F800000ULL
#define NEG12_C  0xBF800000BF800000ULL

#define F2_ADD(o, a, b)    asm("add.rn.f32x2 %0, %1, %2;" : "=l"(o) : "l"(a), "l"(b))
#define F2_MUL(o, a, b)    asm("mul.rn.f32x2 %0, %1, %2;" : "=l"(o) : "l"(a), "l"(b))
#define F2_FMA(o, a, b, c) asm("fma.rn.f32x2 %0, %1, %2, %3;" : "=l"(o) : "l"(a), "l"(b), "l"(c))
#define F2_PACK(o, lo, hi) asm("mov.b64 %0, {%1, %2};" : "=l"(o) : "f"(lo), "f"(hi))
#define F2_UNPACK(lo, hi, in) asm("mov.b64 {%0, %1}, %2;" : "=f"(lo), "=f"(hi) : "l"(in))

// Per-(neuron, block) partial: {k, first_spike_l, last_spike_l, bits(sum_d2)}
__device__ int4  g_partial[NNEUR * NBLK];
__device__ float g_accum;
__device__ int   g_cnt;

// Ordered combine of two ADJACENT segments (a before b). Identity: k == 0.
__device__ __forceinline__ int4 comb(int4 a, int4 b) {
    if (b.x == 0) return a;
    if (a.x == 0) return b;
    float d = (float)(b.y - a.z);                       // cross-segment ISI
    float s = __int_as_float(a.w) + __int_as_float(b.w) + d * d;
    return make_int4(a.x + b.x, a.y, b.z, __float_as_int(s));
}

// Packed update for one neuron pair p. v in {0,1} per lane.
// gp: gap counter; s: sum d^2 (incl. bogus first gap); kf: spike count;
// ns: 1 until first spike then 0; lz: #rows before first spike.
#define PEP(p, vlo, vhi)                         \
    do {                                         \
        u64 v2_, d2_, m2_, t2_;                  \
        F2_PACK(v2_, (vlo), (vhi));              \
        F2_ADD(d2_, gp2[p], one2);               \
        F2_MUL(m2_, v2_, d2_);                   \
        F2_FMA(s2[p], m2_, d2_, s2[p]);          \
        F2_FMA(gp2[p], m2_, neg12, d2_);         \
        F2_ADD(kf2[p], kf2[p], v2_);             \
        F2_MUL(t2_, v2_, ns2[p]);                \
        F2_FMA(ns2[p], t2_, neg12, ns2[p]);      \
        F2_ADD(lz2[p], lz2[p], ns2[p]);          \
    } while (0)

#define PROW(vec)                      \
    do {                               \
        PEP(0, (vec).x, (vec).y);      \
        PEP(1, (vec).z, (vec).w);      \
    } while (0)

__global__ __launch_bounds__(512, 2) void cv_pass1(const float* __restrict__ x) {
    const int tid   = threadIdx.x;
    const int slice = tid >> 7;          // 0..3 : row-slice within block
    const int g     = tid & (NG - 1);    // 0..127: neuron group (4 neurons)
    const int sc    = blockIdx.x * 4 + slice;      // global sub-chunk
    if (blockIdx.x == 0 && tid == 0) { g_accum = 0.0f; g_cnt = 0; }

    const int start = sc * RB + min(sc, RREM);
    const int rows  = RB + (sc < RREM ? 1 : 0);    // 27 or 28

    const u64 one2  = ONE2_C;
    const u64 neg12 = NEG12_C;
    u64 gp2[2] = {0ULL, 0ULL};
    u64 s2[2]  = {0ULL, 0ULL};
    u64 kf2[2] = {0ULL, 0ULL};
    u64 ns2[2] = {ONE2_C, ONE2_C};
    u64 lz2[2] = {0ULL, 0ULL};

    const float4* p = (const float4*)x + (size_t)start * NG + g;
    int r = 0;

    // prefetch batch 0 (rows >= 27 > 4 always)
    float4 b0 = p[0 * NG], b1 = p[1 * NG], b2 = p[2 * NG], b3 = p[3 * NG];
    p += 4 * NG;

    while (r + 8 <= rows) {
        // prefetch next batch BEFORE processing current (loads stay in flight)
        float4 c0 = p[0 * NG], c1 = p[1 * NG], c2 = p[2 * NG], c3 = p[3 * NG];
        p += 4 * NG;
        PROW(b0); PROW(b1); PROW(b2); PROW(b3);
        b0 = c0; b1 = c1; b2 = c2; b3 = c3;
        r += 4;
    }
    // drain prefetched batch
    PROW(b0); PROW(b1); PROW(b2); PROW(b3);
    r += 4;
    // tail (0..3 rows)
    for (; r < rows; ++r) {
        float4 v = p[0];
        p += NG;
        PROW(v);
    }

    // Flush: t_first = lz+1, t_last = rows - gp (1-based local);
    // subtract bogus first gap^2 (= t_first^2) from s.
    __shared__ int4 sp[4][NNEUR];
#pragma unroll
    for (int pr = 0; pr < 2; ++pr) {
        float kfl, kfh, gpl, gph, ssl, ssh, lzl, lzh;
        F2_UNPACK(kfl, kfh, kf2[pr]);
        F2_UNPACK(gpl, gph, gp2[pr]);
        F2_UNPACK(ssl, ssh, s2[pr]);
        F2_UNPACK(lzl, lzh, lz2[pr]);
        float kfj[2] = {kfl, kfh}, gpj[2] = {gpl, gph};
        float ssj[2] = {ssl, ssh}, lzj[2] = {lzl, lzh};
#pragma unroll
        for (int h = 0; h < 2; ++h) {
            const int j = pr * 2 + h;
            int kk = (int)kfj[h];
            int4 part;
            if (kk > 0) {
                float tf1 = lzj[h] + 1.0f;            // t_first, 1-based local
                int tlast = rows - (int)gpj[h];       // 1-based local
                float sc_ = ssj[h] - tf1 * tf1;
                part = make_int4(kk, start + (int)lzj[h], start + tlast - 1,
                                 __float_as_int(sc_));
            } else {
                part = make_int4(0, 0, 0, 0);
            }
            sp[slice][g * 4 + j] = part;
        }
    }
    __syncthreads();

    if (slice == 0) {
#pragma unroll
        for (int j = 0; j < 4; ++j) {
            const int n = g * 4 + j;
            int4 a = sp[0][n];
            a = comb(a, sp[1][n]);
            a = comb(a, sp[2][n]);
            a = comb(a, sp[3][n]);
            g_partial[(size_t)n * NBLK + blockIdx.x] = a;
        }
    }
}

// One block per neuron: adjacent-pair tree over the 296 block partials.
__global__ __launch_bounds__(RED_THREADS) void cv_pass2(const float* __restrict__ target) {
    const int n   = blockIdx.x;
    const int tid = threadIdx.x;

    __shared__ int4 sm[RED_THREADS];

    int4 part = make_int4(0, 0, 0, 0);
    if (tid < NBLK)
        part = g_partial[(size_t)n * NBLK + tid];   // coalesced along chunk axis
    sm[tid] = part;
    __syncthreads();

    for (int lvl = RED_THREADS; lvl > 1; lvl >>= 1) {
        const int half = lvl >> 1;
        int4 res;
        if (tid < half)
            res = comb(sm[2 * tid], sm[2 * tid + 1]);   // adjacent -> contiguous
        __syncthreads();
        if (tid < half)
            sm[tid] = res;
        __syncthreads();
    }

    if (tid == 0) {
        int4 tot = sm[0];
        int kk = tot.x;
        if (kk >= 3) {
            float cnt   = (float)(kk - 1);            // number of ISIs
            float sum_d = (float)(tot.z - tot.y);     // telescoping sum of ISIs
            float mean  = sum_d / cnt;
            if (mean > 0.0f) {
                // sum((d-mean)^2) = sum_d2 - 2*mean*sum_d + cnt*mean^2
                float var = (__int_as_float(tot.w) - 2.0f * mean * sum_d + cnt * mean * mean)
                            / fmaxf(cnt - 1.0f, 1.0f);   // unbiased (correction=1)
                float stdv = (var > 0.0f) ? sqrtf(var) : 0.0f;
                float cv   = stdv / fmaxf(mean, 1e-12f);
                float diff = cv - target[n];
                atomicAdd(&g_accum, diff * diff);
                atomicAdd(&g_cnt, 1);
            }
        }
    }
}

__global__ void cv_pass3(float* __restrict__ out) {
    out[0] = g_accum / fmaxf((float)g_cnt, 1.0f);
}

extern "C" void kernel_launch(void* const* d_in, const int* in_sizes, int n_in,
                              void* d_out, int out_size) {
    const float* spikes = (const float*)d_in[0];   // (16, 2000, 512) float32
    const float* target = (const float*)d_in[1];   // (512,) float32
    float* out = (float*)d_out;                    // scalar float32

    cv_pass1<<<NBLK, 512>>>(spikes);
    cv_pass2<<<NNEUR, RED_THREADS>>>(target);
    cv_pass3<<<1, 1>>>(out);
}